// round 15
// baseline (speedup 1.0000x reference)
#include <cuda_runtime.h>
#include <cuda_fp16.h>
#include <cstdint>
#include <math.h>

// FlowMatching: per-batch Gaussian blur (separable, K=9, sigma=0.1+0.9*t[b],
// dynamic radius mask r=ceil(4*sigma), zero padding) + lerp t*blur + (1-t)*x.
// x1: [128, 3, 512, 512] fp32, t: [128] fp32, out: same as x1.
//
// R14: R13 (cp.async double-buffered strip pipeline, 152.6us) + occupancy
// push. 53.8KB smem already allows 4 blocks/SM; regs were the blocker (78).
// Diet: packed weight pairs wp[] rebuilt per phase-V from scalars (live range
// V-only instead of whole loop, frees ~18 regs at H), launch_bounds(256,4).
// P_TILES 16 (full column): half the prologue bubbles, 1536 blocks.

#define H 512
#define W 512
#define TW 128
#define TH 32
#define RAD 4
#define KS 9
#define P_TILES 16
#define RAW_W 136                     // 128 + 2*4 halo cols
#define RAW_H 40                      // 32 + 2*4 halo rows
#define RAW_BYTES (RAW_H * RAW_W * 4) // 21760
#define SH_BYTES  (RAW_H * TW * 2)    // 10240 (fp16 h-filtered)
#define SMEM_BYTES (2 * RAW_BYTES + SH_BYTES)  // 53760

typedef unsigned long long u64;
typedef unsigned int u32;

__device__ __forceinline__ u64 packf2(float lo, float hi) {
    u64 r;
    asm("mov.b64 %0, {%1, %2};" : "=l"(r) : "f"(lo), "f"(hi));
    return r;
}
__device__ __forceinline__ u64 ffma2(u64 a, u64 b, u64 c) {
    u64 d;
    asm("fma.rn.f32x2 %0, %1, %2, %3;" : "=l"(d) : "l"(a), "l"(b), "l"(c));
    return d;
}
__device__ __forceinline__ u64 mulf2(u64 a, u64 b) {
    u64 d;
    asm("mul.rn.f32x2 %0, %1, %2;" : "=l"(d) : "l"(a), "l"(b));
    return d;
}

// prefetch one 40x136 raw tile (float) into smem via cp.async, zero-filling
// out-of-image quads (src_size=0). 40*34 = 1360 16B ops across 256 threads.
__device__ __forceinline__ void prefetch_tile(const float* __restrict__ pin,
                                              int y0, int x0,
                                              float* rawbuf, int tid)
{
    u32 sbase = (u32)__cvta_generic_to_shared(rawbuf);
    #pragma unroll
    for (int k = 0; k < 6; k++) {
        int idx = tid + k * 256;
        if (idx < RAW_H * 34) {
            int row = idx / 34;
            int c   = idx - row * 34;          // 0..33 quad within row
            int gy  = y0 - RAD + row;
            int gxq = x0 - RAD + c * 4;        // 16B-aligned global x
            bool ok = (gy >= 0) && (gy < H) && (gxq >= 0) && (gxq < W);
            const float* src = ok ? (pin + gy * W + gxq) : pin;
            unsigned sz = ok ? 16u : 0u;
            u32 dst = sbase + (u32)(row * RAW_W + c * 4) * 4u;
            asm volatile("cp.async.cg.shared.global [%0], [%1], 16, %2;"
                         :: "r"(dst), "l"(src), "r"(sz));
        }
    }
}

__global__ __launch_bounds__(256, 4)
void flowmatch_blur_kernel(const float* __restrict__ x1,
                           const float* __restrict__ t,
                           float* __restrict__ out)
{
    extern __shared__ __align__(16) unsigned char smem[];
    float*  raw0 = (float*)(smem);
    float*  raw1 = (float*)(smem + RAW_BYTES);
    __half* s_h  = (__half*)(smem + 2 * RAW_BYTES);

    const int tid   = threadIdx.x;
    const int plane = blockIdx.z;              // b*3 + c, 384 planes
    const int b     = plane / 3;
    const int x0    = blockIdx.x * TW;
    const int ystrip = 0;                      // full-column strip

    const float tv = __ldg(&t[b]);

    // ---- normalized 1D gaussian weights (scalars live whole kernel) ----
    float w0,w1,w2,w3,w4,w5,w6,w7,w8;
    {
        float sigma  = __fadd_rn(0.1f, __fmul_rn(tv, 0.9f));
        float r      = ceilf(__fmul_rn(4.0f, sigma));
        float inv2s2 = 1.0f / (2.0f * sigma * sigma);
        float wl[KS];
        float sum = 0.0f;
        #pragma unroll
        for (int i = 0; i < KS; i++) {
            float c = (float)(i - RAD);
            float v = (fabsf(c) <= r) ? expf(-c * c * inv2s2) : 0.0f;
            wl[i] = v;
            sum += v;
        }
        float inv = 1.0f / sum;
        w0=wl[0]*inv; w1=wl[1]*inv; w2=wl[2]*inv; w3=wl[3]*inv; w4=wl[4]*inv;
        w5=wl[5]*inv; w6=wl[6]*inv; w7=wl[7]*inv; w8=wl[8]*inv;
    }

    const float* pin  = x1  + (size_t)plane * (H * W);
    float*       pout = out + (size_t)plane * (H * W);

    const int q  = tid & 31;
    const int r0 = tid >> 5;

    // prologue: prefetch tile 0
    prefetch_tile(pin, ystrip, x0, raw0, tid);
    asm volatile("cp.async.commit_group;");

    for (int i = 0; i < P_TILES; i++) {
        const int y0 = ystrip + i * TH;
        float* cur = (i & 1) ? raw1 : raw0;
        float* nxt = (i & 1) ? raw0 : raw1;

        // wait for tile i's data; sync also guarantees V(i-1) finished
        // reading `nxt` before we overwrite it below.
        asm volatile("cp.async.wait_group 0;");
        __syncthreads();

        if (i + 1 < P_TILES) {
            prefetch_tile(pin, y0 + TH, x0, nxt, tid);
            asm volatile("cp.async.commit_group;");
        }

        // ---- Phase H: 3 LDS.128 per quad from raw, scalar 9-tap, fp16 STS ----
        #pragma unroll
        for (int k = 0; k < 5; k++) {
            int idx = tid + k * 256;       // 0..1279
            int row = idx >> 5;            // 0..39
            int qx  = idx & 31;            // 0..31
            const float* rp = cur + row * RAW_W + qx * 4;
            float4 A  = *reinterpret_cast<const float4*>(rp);
            float4 Bv = *reinterpret_cast<const float4*>(rp + 4);
            float4 Cv = *reinterpret_cast<const float4*>(rp + 8);

            float f0=A.x,  f1=A.y,  f2=A.z,  f3=A.w;
            float f4=Bv.x, f5=Bv.y, f6=Bv.z, f7=Bv.w;
            float f8=Cv.x, f9=Cv.y, f10=Cv.z, f11=Cv.w;

            float4 o;
            o.x = w0*f0 + w1*f1 + w2*f2 + w3*f3 + w4*f4 + w5*f5 + w6*f6 + w7*f7 + w8*f8;
            o.y = w0*f1 + w1*f2 + w2*f3 + w3*f4 + w4*f5 + w5*f6 + w6*f7 + w7*f8 + w8*f9;
            o.z = w0*f2 + w1*f3 + w2*f4 + w3*f5 + w4*f6 + w5*f7 + w6*f8 + w7*f9 + w8*f10;
            o.w = w0*f3 + w1*f4 + w2*f5 + w3*f6 + w4*f7 + w5*f8 + w6*f9 + w7*f10 + w8*f11;

            __half2 h01 = __floats2half2_rn(o.x, o.y);
            __half2 h23 = __floats2half2_rn(o.z, o.w);
            uint2 packed;
            packed.x = *reinterpret_cast<unsigned*>(&h01);
            packed.y = *reinterpret_cast<unsigned*>(&h23);
            *reinterpret_cast<uint2*>(&s_h[row * TW + qx * 4]) = packed;
        }

        __syncthreads();

        // ---- Phase V: FFMA2 vertical 9-tap, rolling 12-row window,
        //      4 stacked quads; lerp orig from raw smem ----
        {
            const int xq    = q * 4;
            const int ybase = r0 * 4;      // 0,4,...,28
            const float omt = 1.0f - tv;

            // packed weight pairs rebuilt here: live range = phase V only
            u64 wp[KS];
            wp[0]=packf2(w0,w0); wp[1]=packf2(w1,w1); wp[2]=packf2(w2,w2);
            wp[3]=packf2(w3,w3); wp[4]=packf2(w4,w4); wp[5]=packf2(w5,w5);
            wp[6]=packf2(w6,w6); wp[7]=packf2(w7,w7); wp[8]=packf2(w8,w8);

            u64 a0lo=0, a0hi=0, a1lo=0, a1hi=0,
                a2lo=0, a2hi=0, a3lo=0, a3hi=0;

            #pragma unroll
            for (int r = 0; r < 12; r++) {
                uint2 rawh = *reinterpret_cast<const uint2*>(&s_h[(ybase + r) * TW + xq]);
                __half2 h01 = *reinterpret_cast<__half2*>(&rawh.x);
                __half2 h23 = *reinterpret_cast<__half2*>(&rawh.y);
                float2 lo = __half22float2(h01);
                float2 hi = __half22float2(h23);
                u64 plo = packf2(lo.x, lo.y);
                u64 phi = packf2(hi.x, hi.y);

                if (r <= 8) {
                    a0lo = ffma2(wp[r], plo, a0lo);
                    a0hi = ffma2(wp[r], phi, a0hi);
                }
                if (r >= 1 && r <= 9) {
                    a1lo = ffma2(wp[r-1], plo, a1lo);
                    a1hi = ffma2(wp[r-1], phi, a1hi);
                }
                if (r >= 2 && r <= 10) {
                    a2lo = ffma2(wp[r-2], plo, a2lo);
                    a2hi = ffma2(wp[r-2], phi, a2hi);
                }
                if (r >= 3) {                  // r max 11 -> weight idx max 8
                    a3lo = ffma2(wp[r-3], plo, a3lo);
                    a3hi = ffma2(wp[r-3], phi, a3hi);
                }
            }

            u64 alo[4] = {a0lo, a1lo, a2lo, a3lo};
            u64 ahi[4] = {a0hi, a1hi, a2hi, a3hi};

            const u64 tvp  = packf2(tv, tv);
            const u64 omtp = packf2(omt, omt);

            #pragma unroll
            for (int j = 0; j < 4; j++) {
                int ly = ybase + j;
                // orig = raw[ly+4][xq+4 ..] (interior of raw tile), 16B aligned
                ulonglong2 og = *reinterpret_cast<const ulonglong2*>(
                    cur + (ly + RAD) * RAW_W + xq + RAD);

                ulonglong2 res;
                res.x = ffma2(tvp, alo[j], mulf2(omtp, og.x));
                res.y = ffma2(tvp, ahi[j], mulf2(omtp, og.y));

                *reinterpret_cast<ulonglong2*>(pout + (size_t)(y0 + ly) * W + x0 + xq) = res;
            }
        }
    }
}

extern "C" void kernel_launch(void* const* d_in, const int* in_sizes, int n_in,
                              void* d_out, int out_size)
{
    const float* x1 = (const float*)d_in[0];
    const float* t  = (const float*)d_in[1];
    float* out      = (float*)d_out;

    cudaFuncSetAttribute(flowmatch_blur_kernel,
                         cudaFuncAttributeMaxDynamicSharedMemorySize, SMEM_BYTES);

    // 4 x-tiles, full-column strips (16 tiles), 384 planes = 1536 blocks
    dim3 grid(W / TW, 1, 384);
    dim3 block(256);
    flowmatch_blur_kernel<<<grid, block, SMEM_BYTES>>>(x1, t, out);
}